// round 2
// baseline (speedup 1.0000x reference)
#include <cuda_runtime.h>

#define NN 100000
#define FF 128
#define HH 128
#define ZZ 64
#define EE 1600000
#define EPOS 200000

// ---- scratch (static device globals; 16B aligned for vector ld/red) ----
__device__ __align__(16) float g_deg[NN];         // deg -> dinv in place
__device__ __align__(16) float g_hs1[NN * HH];    // (x@W1)*dinv[row]
__device__ __align__(16) float g_acc1[NN * HH];   // layer-1 accumulator (init = hs1 via gemm epilogue)
__device__ __align__(16) float g_h[NN * HH];      // relu output
__device__ __align__(16) float g_hs2[NN * ZZ];    // (h@W2)*dinv[row]
__device__ __align__(16) float g_acc2[NN * ZZ];   // layer-2 accumulator
__device__ __align__(16) float g_lat[NN * ZZ];    // latent

// ---------------- degree / dinv ----------------
__global__ void deg_init_k() {
    int i = blockIdx.x * blockDim.x + threadIdx.x;
    if (i < NN) g_deg[i] = 1.0f;  // self-loop
}

__global__ void deg_count_k(const int* __restrict__ ei) {
    int e = blockIdx.x * blockDim.x + threadIdx.x;
    if (e < EE) atomicAdd(&g_deg[ei[EE + e]], 1.0f);
}

__global__ void dinv_k() {
    int i = blockIdx.x * blockDim.x + threadIdx.x;
    if (i < NN) g_deg[i] = rsqrtf(g_deg[i]);  // deg >= 1 always
}

// ---------------- GEMM: out = (X @ W) * dinv[row], stored to two buffers ----------------
// Block tile: 64 rows x NC cols, 256 threads, per-thread 8 rows x (NC/32) cols.
template <int NC>
__device__ __forceinline__ void gemm_body(const float* __restrict__ X,
                                          const float* __restrict__ W,
                                          float* __restrict__ out1,
                                          float* __restrict__ out2) {
    constexpr int CPT = NC / 32;  // cols per thread (4 or 2)
    __shared__ __align__(16) float Xs[64 * 32];
    __shared__ __align__(16) float Ws[32 * NC];

    const int tid = threadIdx.x;
    const int tx = tid & 31;
    const int ty = tid >> 5;
    const int row0 = blockIdx.x * 64;

    float acc[8][CPT];
#pragma unroll
    for (int i = 0; i < 8; i++)
#pragma unroll
        for (int j = 0; j < CPT; j++) acc[i][j] = 0.0f;

    for (int kb = 0; kb < FF; kb += 32) {
        // load X tile [64][32]
#pragma unroll
        for (int i = 0; i < 8; i++) {
            int r = ty + i * 8;
            int gr = row0 + r;
            Xs[r * 32 + tx] = (gr < NN) ? X[(long)gr * FF + kb + tx] : 0.0f;
        }
        // load W tile [32][NC] as float4
#pragma unroll
        for (int i = 0; i < CPT; i++) {
            int idx = (tid + i * 256) * 4;
            int kk = idx / NC;
            int c = idx % NC;
            *(float4*)&Ws[kk * NC + c] = *(const float4*)&W[(long)(kb + kk) * NC + c];
        }
        __syncthreads();
#pragma unroll
        for (int kk = 0; kk < 32; kk++) {
            float b[CPT];
            if (CPT == 4) {
                float4 t = *(const float4*)&Ws[kk * NC + tx * 4];
                b[0] = t.x; b[1] = t.y; b[2] = t.z; b[3] = t.w;
            } else {
                float2 t = *(const float2*)&Ws[kk * NC + tx * 2];
                b[0] = t.x; b[1] = t.y;
            }
            float a[8];
#pragma unroll
            for (int i = 0; i < 8; i++) a[i] = Xs[(ty * 8 + i) * 32 + kk];
#pragma unroll
            for (int i = 0; i < 8; i++)
#pragma unroll
                for (int j = 0; j < CPT; j++) acc[i][j] = fmaf(a[i], b[j], acc[i][j]);
        }
        __syncthreads();
    }
    // epilogue: scale by dinv[row], dual store
#pragma unroll
    for (int i = 0; i < 8; i++) {
        int gr = row0 + ty * 8 + i;
        if (gr < NN) {
            float s = g_deg[gr];
#pragma unroll
            for (int j = 0; j < CPT; j++) {
                float v = acc[i][j] * s;
                long o = (long)gr * NC + tx * CPT + j;
                out1[o] = v;
                out2[o] = v;
            }
        }
    }
}

__global__ void gemm1_k(const float* __restrict__ x, const float* __restrict__ W1) {
    gemm_body<HH>(x, W1, g_hs1, g_acc1);
}
__global__ void gemm2_k(const float* __restrict__ W2) {
    gemm_body<ZZ>(g_h, W2, g_hs2, g_acc2);
}

// ---------------- edge scatter: acc[dst] += hs[src], one warp per edge ----------------
template <int C>
__device__ __forceinline__ void scatter_body(const int* __restrict__ ei,
                                             const float* __restrict__ hs,
                                             float* __restrict__ acc) {
    int gt = blockIdx.x * blockDim.x + threadIdx.x;
    int w = gt >> 5;
    int lane = gt & 31;
    if (w >= EE) return;
    int src = ei[w];
    int dst = ei[EE + w];
    if (C == 128) {
        float4 v = *(const float4*)&hs[(long)src * 128 + lane * 4];
        float* p = &acc[(long)dst * 128 + lane * 4];
        asm volatile("red.global.add.v4.f32 [%0], {%1,%2,%3,%4};"
                     :: "l"(p), "f"(v.x), "f"(v.y), "f"(v.z), "f"(v.w) : "memory");
    } else {
        float2 v = *(const float2*)&hs[(long)src * 64 + lane * 2];
        float* p = &acc[(long)dst * 64 + lane * 2];
        asm volatile("red.global.add.v2.f32 [%0], {%1,%2};"
                     :: "l"(p), "f"(v.x), "f"(v.y) : "memory");
    }
}

__global__ void scatter1_k(const int* __restrict__ ei) { scatter_body<128>(ei, g_hs1, g_acc1); }
__global__ void scatter2_k(const int* __restrict__ ei) { scatter_body<64>(ei, g_hs2, g_acc2); }

// ---------------- finalize layers ----------------
__global__ void fin1_k(const float* __restrict__ b1) {
    int i = blockIdx.x * blockDim.x + threadIdx.x;
    if (i < NN * HH) {
        int row = i >> 7;
        int c = i & 127;
        float v = g_deg[row] * g_acc1[i] + b1[c];
        g_h[i] = fmaxf(v, 0.0f);
    }
}

__global__ void fin2_k(const float* __restrict__ b2) {
    int i = blockIdx.x * blockDim.x + threadIdx.x;
    if (i < NN * ZZ) {
        int row = i >> 6;
        int c = i & 63;
        g_lat[i] = g_deg[row] * g_acc2[i] + b2[c];
    }
}

// ---------------- decoder: one warp per edge pair ----------------
__global__ void decode_k(const int* __restrict__ pe,
                         const int* __restrict__ ne,
                         float* __restrict__ out) {
    int gt = blockIdx.x * blockDim.x + threadIdx.x;
    int w = gt >> 5;
    int lane = gt & 31;
    if (w >= 2 * EPOS) return;
    int a, b;
    if (w < EPOS) {
        a = pe[w];
        b = pe[EPOS + w];
    } else {
        int k = w - EPOS;
        a = ne[k];
        b = ne[EPOS + k];
    }
    float2 u = *(const float2*)&g_lat[(long)a * 64 + lane * 2];
    float2 v = *(const float2*)&g_lat[(long)b * 64 + lane * 2];
    float s = u.x * v.x + u.y * v.y;
#pragma unroll
    for (int o = 16; o > 0; o >>= 1) s += __shfl_xor_sync(0xffffffffu, s, o);
    if (lane == 0) out[w] = s;
}

// ---------------- launch ----------------
extern "C" void kernel_launch(void* const* d_in, const int* in_sizes, int n_in,
                              void* d_out, int out_size) {
    const float* x = (const float*)d_in[0];
    const float* W1 = (const float*)d_in[1];
    const float* b1 = (const float*)d_in[2];
    const float* W2 = (const float*)d_in[3];
    const float* b2 = (const float*)d_in[4];
    const int* ei = (const int*)d_in[5];
    const int* pe = (const int*)d_in[6];
    const int* ne = (const int*)d_in[7];
    float* out = (float*)d_out;

    deg_init_k<<<(NN + 255) / 256, 256>>>();
    deg_count_k<<<(EE + 255) / 256, 256>>>(ei);
    dinv_k<<<(NN + 255) / 256, 256>>>();

    gemm1_k<<<(NN + 63) / 64, 256>>>(x, W1);
    scatter1_k<<<(EE / 8), 256>>>(ei);  // EE*32/256 = EE/8 exactly
    fin1_k<<<(NN * HH + 255) / 256, 256>>>(b1);

    gemm2_k<<<(NN + 63) / 64, 256>>>(W2);
    scatter2_k<<<(EE / 8), 256>>>(ei);
    fin2_k<<<(NN * ZZ + 255) / 256, 256>>>(b2);

    decode_k<<<(2 * EPOS * 32 + 255) / 256, 256>>>(pe, ne, out);
}

// round 3
// speedup vs baseline: 1.7752x; 1.7752x over previous
#include <cuda_runtime.h>

#define NN 100000
#define FF 128
#define HH 128
#define ZZ 64
#define EE 1600000
#define EPOS 200000
#define NCHUNK ((NN + 255) / 256)   // 391

// ---- scratch (static device globals) ----
__device__ __align__(16) int   g_cnt[NN];          // dst histogram (no self-loop)
__device__ __align__(16) int   g_bsum[512];
__device__ __align__(16) int   g_boff[512];
__device__ __align__(16) int   g_rowstart[NN + 1];
__device__ __align__(16) int   g_cursor[NN];
__device__ __align__(16) int   g_csr[EE];          // src ids sorted by dst
__device__ __align__(16) float g_dinv[NN];
__device__ __align__(16) float g_hs1[NN * HH];     // (x@W1)*dinv[row]
__device__ __align__(16) float g_h[NN * HH];       // relu output
__device__ __align__(16) float g_hs2[NN * ZZ];     // (h@W2)*dinv[row]
__device__ __align__(16) float g_lat[NN * ZZ];     // latent

// ---------------- histogram / dinv ----------------
__global__ void cnt_init_k() {
    int i = blockIdx.x * blockDim.x + threadIdx.x;
    if (i < NN) g_cnt[i] = 0;
}

__global__ void cnt_count_k(const int* __restrict__ ei) {
    int e = blockIdx.x * blockDim.x + threadIdx.x;
    if (e < EE) atomicAdd(&g_cnt[ei[EE + e]], 1);
}

__global__ void dinv_k() {
    int i = blockIdx.x * blockDim.x + threadIdx.x;
    if (i < NN) g_dinv[i] = rsqrtf((float)(g_cnt[i] + 1));  // +1 self-loop
}

// ---------------- scan (3 small kernels) ----------------
__global__ void scan_bsum_k() {
    __shared__ int sh[256];
    int i = blockIdx.x * 256 + threadIdx.x;
    sh[threadIdx.x] = (i < NN) ? g_cnt[i] : 0;
    __syncthreads();
    for (int o = 128; o > 0; o >>= 1) {
        if (threadIdx.x < o) sh[threadIdx.x] += sh[threadIdx.x + o];
        __syncthreads();
    }
    if (threadIdx.x == 0) g_bsum[blockIdx.x] = sh[0];
}

__global__ void scan_boff_k() {  // 1 block, 512 threads; exclusive scan of g_bsum
    __shared__ int sh[512];
    int t = threadIdx.x;
    int v = (t < NCHUNK) ? g_bsum[t] : 0;
    sh[t] = v;
    __syncthreads();
    for (int o = 1; o < 512; o <<= 1) {
        int add = (t >= o) ? sh[t - o] : 0;
        __syncthreads();
        sh[t] += add;
        __syncthreads();
    }
    g_boff[t] = sh[t] - v;  // exclusive
}

__global__ void scan_final_k() {
    __shared__ int sh[256];
    int t = threadIdx.x;
    int i = blockIdx.x * 256 + t;
    int v = (i < NN) ? g_cnt[i] : 0;
    sh[t] = v;
    __syncthreads();
    for (int o = 1; o < 256; o <<= 1) {
        int add = (t >= o) ? sh[t - o] : 0;
        __syncthreads();
        sh[t] += add;
        __syncthreads();
    }
    if (i < NN) {
        int rs = g_boff[blockIdx.x] + sh[t] - v;  // exclusive
        g_rowstart[i] = rs;
        g_cursor[i] = rs;
        if (i == NN - 1) g_rowstart[NN] = EE;
    }
}

__global__ void csr_fill_k(const int* __restrict__ ei) {
    int e = blockIdx.x * blockDim.x + threadIdx.x;
    if (e < EE) {
        int dst = ei[EE + e];
        int pos = atomicAdd(&g_cursor[dst], 1);
        g_csr[pos] = ei[e];
    }
}

// ---------------- GEMM: out = (X @ W) * dinv[row] ----------------
template <int NC>
__device__ __forceinline__ void gemm_body(const float* __restrict__ X,
                                          const float* __restrict__ W,
                                          float* __restrict__ out) {
    constexpr int CPT = NC / 32;
    __shared__ __align__(16) float Xs[64 * 32];
    __shared__ __align__(16) float Ws[32 * NC];

    const int tid = threadIdx.x;
    const int tx = tid & 31;
    const int ty = tid >> 5;
    const int row0 = blockIdx.x * 64;

    float acc[8][CPT];
#pragma unroll
    for (int i = 0; i < 8; i++)
#pragma unroll
        for (int j = 0; j < CPT; j++) acc[i][j] = 0.0f;

    for (int kb = 0; kb < FF; kb += 32) {
#pragma unroll
        for (int i = 0; i < 8; i++) {
            int r = ty + i * 8;
            int gr = row0 + r;
            Xs[r * 32 + tx] = (gr < NN) ? X[(long)gr * FF + kb + tx] : 0.0f;
        }
#pragma unroll
        for (int i = 0; i < CPT; i++) {
            int idx = (tid + i * 256) * 4;
            int kk = idx / NC;
            int c = idx % NC;
            *(float4*)&Ws[kk * NC + c] = *(const float4*)&W[(long)(kb + kk) * NC + c];
        }
        __syncthreads();
#pragma unroll
        for (int kk = 0; kk < 32; kk++) {
            float b[CPT];
            if (CPT == 4) {
                float4 t = *(const float4*)&Ws[kk * NC + tx * 4];
                b[0] = t.x; b[1] = t.y; b[2] = t.z; b[3] = t.w;
            } else {
                float2 t = *(const float2*)&Ws[kk * NC + tx * 2];
                b[0] = t.x; b[1] = t.y;
            }
            float a[8];
#pragma unroll
            for (int i = 0; i < 8; i++) a[i] = Xs[(ty * 8 + i) * 32 + kk];
#pragma unroll
            for (int i = 0; i < 8; i++)
#pragma unroll
                for (int j = 0; j < CPT; j++) acc[i][j] = fmaf(a[i], b[j], acc[i][j]);
        }
        __syncthreads();
    }
#pragma unroll
    for (int i = 0; i < 8; i++) {
        int gr = row0 + ty * 8 + i;
        if (gr < NN) {
            float s = g_dinv[gr];
#pragma unroll
            for (int j = 0; j < CPT; j++) out[(long)gr * NC + tx * CPT + j] = acc[i][j] * s;
        }
    }
}

__global__ void gemm1_k(const float* __restrict__ x, const float* __restrict__ W1) {
    gemm_body<HH>(x, W1, g_hs1);
}
__global__ void gemm2_k(const float* __restrict__ W2) {
    gemm_body<ZZ>(g_h, W2, g_hs2);
}

// ---------------- gather: one warp per dst node, register accumulation ----------------
__global__ void gather1_k(const float* __restrict__ b1) {
    int gt = blockIdx.x * blockDim.x + threadIdx.x;
    int n = gt >> 5;
    int lane = gt & 31;
    if (n >= NN) return;
    int s = g_rowstart[n];
    int e = g_rowstart[n + 1];

    float4 acc = *(const float4*)&g_hs1[(long)n * 128 + lane * 4];  // self-loop

    for (int base = s; base < e; base += 32) {
        int idx = base + lane;
        int myi = (idx < e) ? g_csr[idx] : 0;
        int cnt = min(32, e - base);
        int j = 0;
        for (; j + 4 <= cnt; j += 4) {
            int s0 = __shfl_sync(0xffffffffu, myi, j);
            int s1 = __shfl_sync(0xffffffffu, myi, j + 1);
            int s2 = __shfl_sync(0xffffffffu, myi, j + 2);
            int s3 = __shfl_sync(0xffffffffu, myi, j + 3);
            float4 v0 = *(const float4*)&g_hs1[(long)s0 * 128 + lane * 4];
            float4 v1 = *(const float4*)&g_hs1[(long)s1 * 128 + lane * 4];
            float4 v2 = *(const float4*)&g_hs1[(long)s2 * 128 + lane * 4];
            float4 v3 = *(const float4*)&g_hs1[(long)s3 * 128 + lane * 4];
            acc.x += (v0.x + v1.x) + (v2.x + v3.x);
            acc.y += (v0.y + v1.y) + (v2.y + v3.y);
            acc.z += (v0.z + v1.z) + (v2.z + v3.z);
            acc.w += (v0.w + v1.w) + (v2.w + v3.w);
        }
        for (; j < cnt; j++) {
            int s0 = __shfl_sync(0xffffffffu, myi, j);
            float4 v = *(const float4*)&g_hs1[(long)s0 * 128 + lane * 4];
            acc.x += v.x; acc.y += v.y; acc.z += v.z; acc.w += v.w;
        }
    }
    float d = g_dinv[n];
    float4 bb = *(const float4*)&b1[lane * 4];
    float4 o;
    o.x = fmaxf(fmaf(d, acc.x, bb.x), 0.0f);
    o.y = fmaxf(fmaf(d, acc.y, bb.y), 0.0f);
    o.z = fmaxf(fmaf(d, acc.z, bb.z), 0.0f);
    o.w = fmaxf(fmaf(d, acc.w, bb.w), 0.0f);
    *(float4*)&g_h[(long)n * 128 + lane * 4] = o;
}

__global__ void gather2_k(const float* __restrict__ b2) {
    int gt = blockIdx.x * blockDim.x + threadIdx.x;
    int n = gt >> 5;
    int lane = gt & 31;
    if (n >= NN) return;
    int s = g_rowstart[n];
    int e = g_rowstart[n + 1];

    float2 acc = *(const float2*)&g_hs2[(long)n * 64 + lane * 2];  // self-loop

    for (int base = s; base < e; base += 32) {
        int idx = base + lane;
        int myi = (idx < e) ? g_csr[idx] : 0;
        int cnt = min(32, e - base);
        int j = 0;
        for (; j + 4 <= cnt; j += 4) {
            int s0 = __shfl_sync(0xffffffffu, myi, j);
            int s1 = __shfl_sync(0xffffffffu, myi, j + 1);
            int s2 = __shfl_sync(0xffffffffu, myi, j + 2);
            int s3 = __shfl_sync(0xffffffffu, myi, j + 3);
            float2 v0 = *(const float2*)&g_hs2[(long)s0 * 64 + lane * 2];
            float2 v1 = *(const float2*)&g_hs2[(long)s1 * 64 + lane * 2];
            float2 v2 = *(const float2*)&g_hs2[(long)s2 * 64 + lane * 2];
            float2 v3 = *(const float2*)&g_hs2[(long)s3 * 64 + lane * 2];
            acc.x += (v0.x + v1.x) + (v2.x + v3.x);
            acc.y += (v0.y + v1.y) + (v2.y + v3.y);
        }
        for (; j < cnt; j++) {
            int s0 = __shfl_sync(0xffffffffu, myi, j);
            float2 v = *(const float2*)&g_hs2[(long)s0 * 64 + lane * 2];
            acc.x += v.x; acc.y += v.y;
        }
    }
    float d = g_dinv[n];
    float2 bb = *(const float2*)&b2[lane * 2];
    float2 o;
    o.x = fmaf(d, acc.x, bb.x);
    o.y = fmaf(d, acc.y, bb.y);
    *(float2*)&g_lat[(long)n * 64 + lane * 2] = o;
}

// ---------------- decoder: one warp per edge pair ----------------
__global__ void decode_k(const int* __restrict__ pe,
                         const int* __restrict__ ne,
                         float* __restrict__ out) {
    int gt = blockIdx.x * blockDim.x + threadIdx.x;
    int w = gt >> 5;
    int lane = gt & 31;
    if (w >= 2 * EPOS) return;
    int a, b;
    if (w < EPOS) {
        a = pe[w];
        b = pe[EPOS + w];
    } else {
        int k = w - EPOS;
        a = ne[k];
        b = ne[EPOS + k];
    }
    float2 u = *(const float2*)&g_lat[(long)a * 64 + lane * 2];
    float2 v = *(const float2*)&g_lat[(long)b * 64 + lane * 2];
    float s = u.x * v.x + u.y * v.y;
#pragma unroll
    for (int o = 16; o > 0; o >>= 1) s += __shfl_xor_sync(0xffffffffu, s, o);
    if (lane == 0) out[w] = s;
}

// ---------------- launch ----------------
extern "C" void kernel_launch(void* const* d_in, const int* in_sizes, int n_in,
                              void* d_out, int out_size) {
    const float* x = (const float*)d_in[0];
    const float* W1 = (const float*)d_in[1];
    const float* b1 = (const float*)d_in[2];
    const float* W2 = (const float*)d_in[3];
    const float* b2 = (const float*)d_in[4];
    const int* ei = (const int*)d_in[5];
    const int* pe = (const int*)d_in[6];
    const int* ne = (const int*)d_in[7];
    float* out = (float*)d_out;

    // CSR build + dinv
    cnt_init_k<<<(NN + 255) / 256, 256>>>();
    cnt_count_k<<<(EE + 255) / 256, 256>>>(ei);
    dinv_k<<<(NN + 255) / 256, 256>>>();
    scan_bsum_k<<<NCHUNK, 256>>>();
    scan_boff_k<<<1, 512>>>();
    scan_final_k<<<NCHUNK, 256>>>();
    csr_fill_k<<<(EE + 255) / 256, 256>>>(ei);

    // layer 1
    gemm1_k<<<(NN + 63) / 64, 256>>>(x, W1);
    gather1_k<<<(NN * 32 + 255) / 256, 256>>>(b1);

    // layer 2
    gemm2_k<<<(NN + 63) / 64, 256>>>(W2);
    gather2_k<<<(NN * 32 + 255) / 256, 256>>>(b2);

    decode_k<<<(2 * EPOS * 32 + 255) / 256, 256>>>(pe, ne, out);
}

// round 7
// speedup vs baseline: 1.7777x; 1.0014x over previous
#include <cuda_runtime.h>

#define NN 100000
#define FF 128
#define HH 128
#define ZZ 64
#define EE 1600000
#define EPOS 200000
#define NCHUNK ((NN + 255) / 256)   // 391

// ---- scratch (static device globals) ----
__device__ __align__(16) int   g_cnt[NN];          // dst histogram (no self-loop)
__device__ __align__(16) int   g_bsum[512];
__device__ __align__(16) int   g_boff[512];
__device__ __align__(16) int   g_rowstart[NN + 1];
__device__ __align__(16) int   g_cursor[NN];
__device__ __align__(16) int   g_csr[EE];          // src ids sorted by dst
__device__ __align__(16) float g_dinv[NN];
__device__ __align__(16) float g_hs1[NN * HH];     // (x@W1)*dinv[row]
__device__ __align__(16) float g_h[NN * HH];       // relu output
__device__ __align__(16) float g_hs2[NN * ZZ];     // (h@W2)*dinv[row]
__device__ __align__(16) float g_lat[NN * ZZ];     // latent

// ---------------- histogram / dinv ----------------
__global__ void cnt_init_k() {
    int i = blockIdx.x * blockDim.x + threadIdx.x;
    if (i < NN) g_cnt[i] = 0;
}

__global__ void cnt_count_k(const int* __restrict__ ei) {
    int e = blockIdx.x * blockDim.x + threadIdx.x;
    if (e < EE) atomicAdd(&g_cnt[ei[EE + e]], 1);
}

__global__ void dinv_k() {
    int i = blockIdx.x * blockDim.x + threadIdx.x;
    if (i < NN) g_dinv[i] = rsqrtf((float)(g_cnt[i] + 1));  // +1 self-loop
}

// ---------------- scan (3 small kernels) ----------------
__global__ void scan_bsum_k() {
    __shared__ int sh[256];
    int i = blockIdx.x * 256 + threadIdx.x;
    sh[threadIdx.x] = (i < NN) ? g_cnt[i] : 0;
    __syncthreads();
    for (int o = 128; o > 0; o >>= 1) {
        if (threadIdx.x < o) sh[threadIdx.x] += sh[threadIdx.x + o];
        __syncthreads();
    }
    if (threadIdx.x == 0) g_bsum[blockIdx.x] = sh[0];
}

__global__ void scan_boff_k() {  // 1 block, 512 threads; exclusive scan of g_bsum
    __shared__ int sh[512];
    int t = threadIdx.x;
    int v = (t < NCHUNK) ? g_bsum[t] : 0;
    sh[t] = v;
    __syncthreads();
    for (int o = 1; o < 512; o <<= 1) {
        int add = (t >= o) ? sh[t - o] : 0;
        __syncthreads();
        sh[t] += add;
        __syncthreads();
    }
    g_boff[t] = sh[t] - v;  // exclusive
}

__global__ void scan_final_k() {
    __shared__ int sh[256];
    int t = threadIdx.x;
    int i = blockIdx.x * 256 + t;
    int v = (i < NN) ? g_cnt[i] : 0;
    sh[t] = v;
    __syncthreads();
    for (int o = 1; o < 256; o <<= 1) {
        int add = (t >= o) ? sh[t - o] : 0;
        __syncthreads();
        sh[t] += add;
        __syncthreads();
    }
    if (i < NN) {
        int rs = g_boff[blockIdx.x] + sh[t] - v;  // exclusive
        g_rowstart[i] = rs;
        g_cursor[i] = rs;
        if (i == NN - 1) g_rowstart[NN] = EE;
    }
}

__global__ void csr_fill_k(const int* __restrict__ ei) {
    int e = blockIdx.x * blockDim.x + threadIdx.x;
    if (e < EE) {
        int dst = ei[EE + e];
        int pos = atomicAdd(&g_cursor[dst], 1);
        g_csr[pos] = ei[e];
    }
}

// ---------------- GEMM: out = (X @ W) * dinv[row]  (round-3 known-good) ----------------
// Block tile: 64 rows x NC cols, 256 threads, per-thread 8 rows x (NC/32) cols.
template <int NC>
__device__ __forceinline__ void gemm_body(const float* __restrict__ X,
                                          const float* __restrict__ W,
                                          float* __restrict__ out) {
    constexpr int CPT = NC / 32;
    __shared__ __align__(16) float Xs[64 * 32];
    __shared__ __align__(16) float Ws[32 * NC];

    const int tid = threadIdx.x;
    const int tx = tid & 31;
    const int ty = tid >> 5;
    const int row0 = blockIdx.x * 64;

    float acc[8][CPT];
#pragma unroll
    for (int i = 0; i < 8; i++)
#pragma unroll
        for (int j = 0; j < CPT; j++) acc[i][j] = 0.0f;

    for (int kb = 0; kb < FF; kb += 32) {
#pragma unroll
        for (int i = 0; i < 8; i++) {
            int r = ty + i * 8;
            int gr = row0 + r;
            Xs[r * 32 + tx] = (gr < NN) ? X[(long)gr * FF + kb + tx] : 0.0f;
        }
#pragma unroll
        for (int i = 0; i < CPT; i++) {
            int idx = (tid + i * 256) * 4;
            int kk = idx / NC;
            int c = idx % NC;
            *(float4*)&Ws[kk * NC + c] = *(const float4*)&W[(long)(kb + kk) * NC + c];
        }
        __syncthreads();
#pragma unroll
        for (int kk = 0; kk < 32; kk++) {
            float b[CPT];
            if (CPT == 4) {
                float4 t = *(const float4*)&Ws[kk * NC + tx * 4];
                b[0] = t.x; b[1] = t.y; b[2] = t.z; b[3] = t.w;
            } else {
                float2 t = *(const float2*)&Ws[kk * NC + tx * 2];
                b[0] = t.x; b[1] = t.y;
            }
            float a[8];
#pragma unroll
            for (int i = 0; i < 8; i++) a[i] = Xs[(ty * 8 + i) * 32 + kk];
#pragma unroll
            for (int i = 0; i < 8; i++)
#pragma unroll
                for (int j = 0; j < CPT; j++) acc[i][j] = fmaf(a[i], b[j], acc[i][j]);
        }
        __syncthreads();
    }
#pragma unroll
    for (int i = 0; i < 8; i++) {
        int gr = row0 + ty * 8 + i;
        if (gr < NN) {
            float s = g_dinv[gr];
#pragma unroll
            for (int j = 0; j < CPT; j++) out[(long)gr * NC + tx * CPT + j] = acc[i][j] * s;
        }
    }
}

__global__ void gemm1_k(const float* __restrict__ x, const float* __restrict__ W1) {
    gemm_body<HH>(x, W1, g_hs1);
}
__global__ void gemm2_k(const float* __restrict__ W2) {
    gemm_body<ZZ>(g_h, W2, g_hs2);
}

// ---------------- gather: one warp per dst node, register accumulation ----------------
__global__ void gather1_k(const float* __restrict__ b1) {
    int gt = blockIdx.x * blockDim.x + threadIdx.x;
    int n = gt >> 5;
    int lane = gt & 31;
    if (n >= NN) return;
    int s = g_rowstart[n];
    int e = g_rowstart[n + 1];

    float4 acc = *(const float4*)&g_hs1[(long)n * 128 + lane * 4];  // self-loop

    for (int base = s; base < e; base += 32) {
        int idx = base + lane;
        int myi = (idx < e) ? g_csr[idx] : 0;
        int cnt = min(32, e - base);
        int j = 0;
        for (; j + 8 <= cnt; j += 8) {
            int ss[8];
#pragma unroll
            for (int q = 0; q < 8; q++) ss[q] = __shfl_sync(0xffffffffu, myi, j + q);
            float4 vv[8];
#pragma unroll
            for (int q = 0; q < 8; q++)
                vv[q] = *(const float4*)&g_hs1[(long)ss[q] * 128 + lane * 4];
#pragma unroll
            for (int q = 0; q < 8; q++) {
                acc.x += vv[q].x;
                acc.y += vv[q].y;
                acc.z += vv[q].z;
                acc.w += vv[q].w;
            }
        }
        for (; j < cnt; j++) {
            int s0 = __shfl_sync(0xffffffffu, myi, j);
            float4 v = *(const float4*)&g_hs1[(long)s0 * 128 + lane * 4];
            acc.x += v.x; acc.y += v.y; acc.z += v.z; acc.w += v.w;
        }
    }
    float d = g_dinv[n];
    float4 bb = *(const float4*)&b1[lane * 4];
    float4 o;
    o.x = fmaxf(fmaf(d, acc.x, bb.x), 0.0f);
    o.y = fmaxf(fmaf(d, acc.y, bb.y), 0.0f);
    o.z = fmaxf(fmaf(d, acc.z, bb.z), 0.0f);
    o.w = fmaxf(fmaf(d, acc.w, bb.w), 0.0f);
    *(float4*)&g_h[(long)n * 128 + lane * 4] = o;
}

__global__ void gather2_k(const float* __restrict__ b2) {
    int gt = blockIdx.x * blockDim.x + threadIdx.x;
    int n = gt >> 5;
    int lane = gt & 31;
    if (n >= NN) return;
    int s = g_rowstart[n];
    int e = g_rowstart[n + 1];

    float2 acc = *(const float2*)&g_hs2[(long)n * 64 + lane * 2];  // self-loop

    for (int base = s; base < e; base += 32) {
        int idx = base + lane;
        int myi = (idx < e) ? g_csr[idx] : 0;
        int cnt = min(32, e - base);
        int j = 0;
        for (; j + 8 <= cnt; j += 8) {
            int ss[8];
#pragma unroll
            for (int q = 0; q < 8; q++) ss[q] = __shfl_sync(0xffffffffu, myi, j + q);
            float2 vv[8];
#pragma unroll
            for (int q = 0; q < 8; q++)
                vv[q] = *(const float2*)&g_hs2[(long)ss[q] * 64 + lane * 2];
#pragma unroll
            for (int q = 0; q < 8; q++) {
                acc.x += vv[q].x;
                acc.y += vv[q].y;
            }
        }
        for (; j < cnt; j++) {
            int s0 = __shfl_sync(0xffffffffu, myi, j);
            float2 v = *(const float2*)&g_hs2[(long)s0 * 64 + lane * 2];
            acc.x += v.x; acc.y += v.y;
        }
    }
    float d = g_dinv[n];
    float2 bb = *(const float2*)&b2[lane * 2];
    float2 o;
    o.x = fmaf(d, acc.x, bb.x);
    o.y = fmaf(d, acc.y, bb.y);
    *(float2*)&g_lat[(long)n * 64 + lane * 2] = o;
}

// ---------------- decoder: one warp per edge pair ----------------
__global__ void decode_k(const int* __restrict__ pe,
                         const int* __restrict__ ne,
                         float* __restrict__ out) {
    int gt = blockIdx.x * blockDim.x + threadIdx.x;
    int w = gt >> 5;
    int lane = gt & 31;
    if (w >= 2 * EPOS) return;
    int a, b;
    if (w < EPOS) {
        a = pe[w];
        b = pe[EPOS + w];
    } else {
        int k = w - EPOS;
        a = ne[k];
        b = ne[EPOS + k];
    }
    float2 u = *(const float2*)&g_lat[(long)a * 64 + lane * 2];
    float2 v = *(const float2*)&g_lat[(long)b * 64 + lane * 2];
    float s = u.x * v.x + u.y * v.y;
#pragma unroll
    for (int o = 16; o > 0; o >>= 1) s += __shfl_xor_sync(0xffffffffu, s, o);
    if (lane == 0) out[w] = s;
}

// ---------------- launch (single stream, round-3 structure) ----------------
extern "C" void kernel_launch(void* const* d_in, const int* in_sizes, int n_in,
                              void* d_out, int out_size) {
    const float* x = (const float*)d_in[0];
    const float* W1 = (const float*)d_in[1];
    const float* b1 = (const float*)d_in[2];
    const float* W2 = (const float*)d_in[3];
    const float* b2 = (const float*)d_in[4];
    const int* ei = (const int*)d_in[5];
    const int* pe = (const int*)d_in[6];
    const int* ne = (const int*)d_in[7];
    float* out = (float*)d_out;

    // CSR build + dinv
    cnt_init_k<<<(NN + 255) / 256, 256>>>();
    cnt_count_k<<<(EE + 255) / 256, 256>>>(ei);
    dinv_k<<<(NN + 255) / 256, 256>>>();
    scan_bsum_k<<<NCHUNK, 256>>>();
    scan_boff_k<<<1, 512>>>();
    scan_final_k<<<NCHUNK, 256>>>();
    csr_fill_k<<<(EE + 255) / 256, 256>>>(ei);

    // layer 1
    gemm1_k<<<(NN + 63) / 64, 256>>>(x, W1);
    gather1_k<<<(NN * 32 + 255) / 256, 256>>>(b1);

    // layer 2
    gemm2_k<<<(NN + 63) / 64, 256>>>(W2);
    gather2_k<<<(NN * 32 + 255) / 256, 256>>>(b2);

    decode_k<<<(2 * EPOS * 32 + 255) / 256, 256>>>(pe, ne, out);
}